// round 1
// baseline (speedup 1.0000x reference)
#include <cuda_runtime.h>
#include <math.h>

#define NNODE 50000
#define NEDGE 800000
#define E2 (NEDGE + NNODE)
#define HID 128
#define HEADS 4
#define CHAN 32
#define NG 512
#define NCLS 10
#define BN_EPS 1e-5f
#define NEG_SLOPE 0.2f

// ---------------- device scratch (no allocation allowed) ----------------
__device__ int   g_deg[NNODE];
__device__ int   g_start[NNODE];
__device__ int   g_cursor[NNODE];
__device__ int   g_csr[E2];
__device__ float g_bufA[NNODE * HID];
__device__ float g_bufB[NNODE * HID];
__device__ float g_hh[NNODE * HID];
__device__ float g_Wt[HID * HID];     // folded weight, transposed [j][k]
__device__ float g_biasv[HID];
__device__ float g_pool[NG * HID];
__device__ float g_tmp[NG * HID];
__device__ float g_Wct[NCLS * HID];
__device__ float g_biasc[NCLS];

// ---------------- CSR construction ----------------
__global__ void k_init_deg(int* deg) {
    int i = blockIdx.x * blockDim.x + threadIdx.x;
    if (i < NNODE) deg[i] = 1;  // self loop
}

__global__ void k_count(const int* __restrict__ dst, int* deg) {
    int i = blockIdx.x * blockDim.x + threadIdx.x;
    if (i < NEDGE) atomicAdd(&deg[dst[i]], 1);
}

__global__ void k_scan(const int* __restrict__ deg, int* __restrict__ start, int n) {
    __shared__ int buf[1024];
    __shared__ int carry;
    int tid = threadIdx.x;
    if (tid == 0) carry = 0;
    __syncthreads();
    for (int base = 0; base < n; base += 1024) {
        int i = base + tid;
        int v = (i < n) ? deg[i] : 0;
        buf[tid] = v;
        __syncthreads();
        for (int off = 1; off < 1024; off <<= 1) {
            int t = (tid >= off) ? buf[tid - off] : 0;
            __syncthreads();
            buf[tid] += t;
            __syncthreads();
        }
        if (i < n) start[i] = carry + buf[tid] - v;
        __syncthreads();
        if (tid == 0) carry += buf[1023];
        __syncthreads();
    }
}

__global__ void k_init_loops(const int* __restrict__ start, int* cursor, int* csr) {
    int i = blockIdx.x * blockDim.x + threadIdx.x;
    if (i < NNODE) {
        int s = start[i];
        csr[s] = i;          // self loop first
        cursor[i] = s + 1;
    }
}

__global__ void k_scatter(const int* __restrict__ src, const int* __restrict__ dst,
                          int* cursor, int* csr) {
    int i = blockIdx.x * blockDim.x + threadIdx.x;
    if (i < NEDGE) {
        int d = dst[i];
        int p = atomicAdd(&cursor[d], 1);
        csr[p] = src[i];
    }
}

// ---------------- BN-fold into weights ----------------
// W [K=128][J=128] row-major -> Wt [j][k] = s[k]*W[k][j];  bias[j] = base[j] + sum_k bn_b[k]*W[k][j]
__global__ void k_fold(const float* __restrict__ W, const float* __restrict__ bn_g,
                       const float* __restrict__ bn_b, const float* __restrict__ base,
                       float* __restrict__ Wt, float* __restrict__ biasv) {
    int j = threadIdx.x;
    float bb = base ? base[j] : 0.f;
    const float inv = rsqrtf(1.f + BN_EPS);
    for (int k = 0; k < HID; k++) {
        float w = W[k * HID + j];
        Wt[j * HID + k] = bn_g[k] * inv * w;
        bb += bn_b[k] * w;
    }
    biasv[j] = bb;
}

// w_cls [128][10] -> Wct [j<10][k], fold bn_hid
__global__ void k_fold_cls(const float* __restrict__ W, const float* __restrict__ bn_g,
                           const float* __restrict__ bn_b, const float* __restrict__ base,
                           float* __restrict__ Wt, float* __restrict__ biasv) {
    int j = threadIdx.x;
    if (j >= NCLS) return;
    float bb = base[j];
    const float inv = rsqrtf(1.f + BN_EPS);
    for (int k = 0; k < HID; k++) {
        float w = W[k * NCLS + j];
        Wt[j * HID + k] = bn_g[k] * inv * w;
        bb += bn_b[k] * w;
    }
    biasv[j] = bb;
}

// ---------------- GEMM: C[M,128] = A[M,128] @ W (Wt transposed) + bias, optional relu ----------
#define GROWS 8
__global__ void k_gemm128(const float* __restrict__ A, const float* __restrict__ Wt,
                          const float* __restrict__ biasv, float* __restrict__ C,
                          int M, int doRelu) {
    __shared__ __align__(16) float sA[GROWS][HID];
    int j = threadIdx.x;
    int row0 = blockIdx.x * GROWS;
#pragma unroll
    for (int r = 0; r < GROWS; r++) {
        int rr = row0 + r;
        sA[r][j] = (rr < M) ? A[rr * HID + j] : 0.f;
    }
    __syncthreads();
    float b = biasv[j];
    float acc[GROWS];
#pragma unroll
    for (int r = 0; r < GROWS; r++) acc[r] = b;
    const float4* w4 = (const float4*)(Wt + j * HID);
#pragma unroll 8
    for (int kk = 0; kk < 32; kk++) {
        float4 w = __ldg(&w4[kk]);
#pragma unroll
        for (int r = 0; r < GROWS; r++) {
            float4 a = ((const float4*)sA[r])[kk];
            acc[r] += a.x * w.x + a.y * w.y + a.z * w.z + a.w * w.w;
        }
    }
#pragma unroll
    for (int r = 0; r < GROWS; r++) {
        int rr = row0 + r;
        if (rr < M) {
            float v = acc[r];
            if (doRelu) v = fmaxf(v, 0.f);
            C[rr * HID + j] = v;
        }
    }
}

// ---------------- SuperGAT attention: warp per destination node, online softmax ------------
__device__ __forceinline__ float grp8_sum(float v) {
    v += __shfl_xor_sync(0xffffffffu, v, 1);
    v += __shfl_xor_sync(0xffffffffu, v, 2);
    v += __shfl_xor_sync(0xffffffffu, v, 4);
    return v;
}

__global__ void k_attn(const float* __restrict__ hh, const int* __restrict__ start,
                       const int* __restrict__ deg, const int* __restrict__ csr,
                       const float* __restrict__ att_l, const float* __restrict__ att_r,
                       const float* __restrict__ b_gat, float* __restrict__ out) {
    int warp = (blockIdx.x * blockDim.x + threadIdx.x) >> 5;
    int lane = threadIdx.x & 31;
    if (warp >= NNODE) return;
    const float4* hh4 = (const float4*)hh;
    float4 hi = __ldg(&hh4[warp * 32 + lane]);
    float4 al = __ldg(&((const float4*)att_l)[lane]);
    float4 ar = __ldg(&((const float4*)att_r)[lane]);
    float ri = hi.x * ar.x + hi.y * ar.y + hi.z * ar.z + hi.w * ar.w;
    ri = grp8_sum(ri);

    float m = -INFINITY, s = 0.f;
    float4 acc = make_float4(0.f, 0.f, 0.f, 0.f);
    int e0 = start[warp];
    int d  = deg[warp];
    for (int e = e0; e < e0 + d; e++) {
        int sn = __ldg(&csr[e]);
        float4 hj = __ldg(&hh4[sn * 32 + lane]);
        float lg = hi.x * hj.x + hi.y * hj.y + hi.z * hj.z + hi.w * hj.w;
        float lj = hj.x * al.x + hj.y * al.y + hj.z * al.z + hj.w * al.w;
        lg = grp8_sum(lg);
        lj = grp8_sum(lj);
        float alpha = (lj + ri) / (1.f + __expf(-lg));   // * sigmoid(logits)
        alpha = alpha > 0.f ? alpha : NEG_SLOPE * alpha; // leaky relu
        float nm = fmaxf(m, alpha);
        float c  = __expf(m - nm);      // first iter: exp(-inf)=0
        float ee = __expf(alpha - nm);
        s = s * c + ee;
        acc.x = acc.x * c + ee * hj.x;
        acc.y = acc.y * c + ee * hj.y;
        acc.z = acc.z * c + ee * hj.z;
        acc.w = acc.w * c + ee * hj.w;
        m = nm;
    }
    float invs = 1.f / (s + 1e-16f);
    float4 bg = __ldg(&((const float4*)b_gat)[lane]);
    float4 o;
    o.x = fmaxf(acc.x * invs + bg.x, 0.f);
    o.y = fmaxf(acc.y * invs + bg.y, 0.f);
    o.z = fmaxf(acc.z * invs + bg.z, 0.f);
    o.w = fmaxf(acc.w * invs + bg.w, 0.f);
    ((float4*)out)[warp * 32 + lane] = o;
}

// ---------------- pooling (batch is sorted) ----------------
__global__ void k_zero(float* p, int n) {
    int i = blockIdx.x * blockDim.x + threadIdx.x;
    if (i < n) p[i] = 0.f;
}

#define PCHUNK 256
__global__ void k_pool(const float* __restrict__ h, const int* __restrict__ batch,
                       float* __restrict__ g) {
    __shared__ int sb[PCHUNK];
    int c = threadIdx.x;  // 128 channels
    int n0 = blockIdx.x * PCHUNK;
    for (int i = c; i < PCHUNK; i += blockDim.x) {
        int idx = n0 + i;
        sb[i] = (idx < NNODE) ? batch[idx] : -1;
    }
    __syncthreads();
    if (sb[0] < 0) return;
    float acc = 0.f;
    int cur = sb[0];
    for (int i = 0; i < PCHUNK; i++) {
        int b = sb[i];
        if (b < 0) break;
        if (b != cur) {
            atomicAdd(&g[cur * HID + c], acc);
            acc = 0.f;
            cur = b;
        }
        acc += h[(n0 + i) * HID + c];
    }
    atomicAdd(&g[cur * HID + c], acc);
}

// ---------------- final logits + log_softmax ----------------
__global__ void k_final(const float* __restrict__ t, const float* __restrict__ Wct,
                        const float* __restrict__ bc, float* __restrict__ out) {
    __shared__ float sr[HID];
    int row = blockIdx.x;
    int lane = threadIdx.x;  // 32
    for (int i = lane; i < HID; i += 32) sr[i] = t[row * HID + i];
    __syncthreads();
    float lg = -INFINITY;
    if (lane < NCLS) {
        float a = bc[lane];
        const float* wr = Wct + lane * HID;
        for (int k = 0; k < HID; k++) a += sr[k] * wr[k];
        lg = a;
    }
    float mx = lg;
    for (int o = 16; o > 0; o >>= 1) mx = fmaxf(mx, __shfl_xor_sync(0xffffffffu, mx, o));
    float ex = (lane < NCLS) ? __expf(lg - mx) : 0.f;
    float sm = ex;
    for (int o = 16; o > 0; o >>= 1) sm += __shfl_xor_sync(0xffffffffu, sm, o);
    if (lane < NCLS) out[row * NCLS + lane] = lg - mx - logf(sm);
}

__global__ void k_zero_tail(float* out, int from, int total) {
    int i = from + blockIdx.x * blockDim.x + threadIdx.x;
    if (i < total) out[i] = 0.f;
}

// ---------------- launch ----------------
static inline void* sym(const void* s) {
    void* p = nullptr;
    cudaGetSymbolAddress(&p, s);
    return p;
}

extern "C" void kernel_launch(void* const* d_in, const int* in_sizes, int n_in,
                              void* d_out, int out_size) {
    const float* x        = (const float*)d_in[0];
    const int*   ei       = (const int*)d_in[1];
    const int*   batch    = (const int*)d_in[2];
    const float* bn_f_g   = (const float*)d_in[3];
    const float* bn_f_b   = (const float*)d_in[4];
    const float* w_feat   = (const float*)d_in[5];
    const float* b_feat   = (const float*)d_in[6];
    const float* bn_c_g   = (const float*)d_in[7];
    const float* bn_c_b   = (const float*)d_in[8];
    const float* w_gat    = (const float*)d_in[9];
    const float* att_l    = (const float*)d_in[10];
    const float* att_r    = (const float*)d_in[11];
    const float* b_gat    = (const float*)d_in[12];
    const float* bn_fc_g  = (const float*)d_in[13];
    const float* bn_fc_b  = (const float*)d_in[14];
    const float* w_fc     = (const float*)d_in[15];
    const float* b_fc     = (const float*)d_in[16];
    const float* bn_h_g   = (const float*)d_in[17];
    const float* bn_h_b   = (const float*)d_in[18];
    const float* w_cls    = (const float*)d_in[19];
    const float* b_cls    = (const float*)d_in[20];
    float* out = (float*)d_out;

    const int* srcp = ei;
    const int* dstp = ei + NEDGE;

    int*   deg    = (int*)sym(g_deg);
    int*   start  = (int*)sym(g_start);
    int*   cursor = (int*)sym(g_cursor);
    int*   csr    = (int*)sym(g_csr);
    float* bufA   = (float*)sym(g_bufA);
    float* bufB   = (float*)sym(g_bufB);
    float* hh     = (float*)sym(g_hh);
    float* Wt     = (float*)sym(g_Wt);
    float* biasv  = (float*)sym(g_biasv);
    float* pool   = (float*)sym(g_pool);
    float* tmp    = (float*)sym(g_tmp);
    float* Wct    = (float*)sym(g_Wct);
    float* biasc  = (float*)sym(g_biasc);

    // CSR build (graph constant across the 3 conv layers)
    k_init_deg<<<(NNODE + 255) / 256, 256>>>(deg);
    k_count<<<(NEDGE + 255) / 256, 256>>>(dstp, deg);
    k_scan<<<1, 1024>>>(deg, start, NNODE);
    k_init_loops<<<(NNODE + 255) / 256, 256>>>(start, cursor, csr);
    k_scatter<<<(NEDGE + 255) / 256, 256>>>(srcp, dstp, cursor, csr);

    // feature layer: relu(BN(x) @ w_feat + b_feat), BN folded
    k_fold<<<1, HID>>>(w_feat, bn_f_g, bn_f_b, b_feat, Wt, biasv);
    k_gemm128<<<(NNODE + GROWS - 1) / GROWS, HID>>>(x, Wt, biasv, bufA, NNODE, 1);

    float* cur = bufA;
    float* nxt = bufB;
    for (int i = 0; i < 3; i++) {
        k_fold<<<1, HID>>>(w_gat + i * HID * HID, bn_c_g + i * HID, bn_c_b + i * HID,
                           nullptr, Wt, biasv);
        k_gemm128<<<(NNODE + GROWS - 1) / GROWS, HID>>>(cur, Wt, biasv, hh, NNODE, 0);
        k_attn<<<(NNODE * 32 + 255) / 256, 256>>>(hh, start, deg, csr,
                                                  att_l + i * HID, att_r + i * HID,
                                                  b_gat + i * HID, nxt);
        float* t2 = cur; cur = nxt; nxt = t2;
    }

    // pooling
    k_zero<<<(NG * HID + 255) / 256, 256>>>(pool, NG * HID);
    k_pool<<<(NNODE + PCHUNK - 1) / PCHUNK, HID>>>(cur, batch, pool);

    // fc: relu(BN(g) @ w_fc + b_fc)
    k_fold<<<1, HID>>>(w_fc, bn_fc_g, bn_fc_b, b_fc, Wt, biasv);
    k_gemm128<<<(NG + GROWS - 1) / GROWS, HID>>>(pool, Wt, biasv, tmp, NG, 1);

    // cls: (BN(t)) @ w_cls + b_cls, then log_softmax
    k_fold_cls<<<1, 32>>>(w_cls, bn_h_g, bn_h_b, b_cls, Wct, biasc);
    k_final<<<NG, 32>>>(tmp, Wct, biasc, out);

    // att_loss (and any padding) = 0
    if (out_size > NG * NCLS) {
        int rem = out_size - NG * NCLS;
        k_zero_tail<<<(rem + 255) / 256, 256>>>(out, NG * NCLS, out_size);
    }
}

// round 2
// speedup vs baseline: 1.7504x; 1.7504x over previous
#include <cuda_runtime.h>
#include <math.h>

#define NNODE 50000
#define NEDGE 800000
#define E2 (NEDGE + NNODE)
#define HID 128
#define NG 512
#define NCLS 10
#define BN_EPS 1e-5f
#define NEG_SLOPE 0.2f
#define NB_SCAN ((NNODE + 1023) / 1024)

// ---------------- device scratch ----------------
__device__ int   g_deg[NNODE];
__device__ int   g_start[NNODE];
__device__ int   g_cursor[NNODE];
__device__ int   g_bsum[64];
__device__ int   g_csr[E2];
__device__ float g_bufA[NNODE * HID];
__device__ float g_bufB[NNODE * HID];
__device__ float g_hh[NNODE * HID];
__device__ float g_li[NNODE * 4];
__device__ float g_ri[NNODE * 4];
__device__ float g_Wf[HID * HID];     // folded weight, [k][j] natural layout
__device__ float g_biasv[HID];
__device__ float g_pool[NG * HID];
__device__ float g_tmp[NG * HID];
__device__ float g_Wct[NCLS * HID];
__device__ float g_biasc[NCLS];

// ---------------- packed f32x2 helpers ----------------
__device__ __forceinline__ unsigned long long pk2(float x) {
    unsigned long long r;
    asm("mov.b64 %0,{%1,%1};" : "=l"(r) : "f"(x));
    return r;
}
__device__ __forceinline__ void fma2(unsigned long long& d, unsigned long long a,
                                     unsigned long long b) {
    asm("fma.rn.f32x2 %0,%1,%2,%0;" : "+l"(d) : "l"(a), "l"(b));
}
__device__ __forceinline__ void unpk2(unsigned long long v, float& lo, float& hi) {
    asm("mov.b64 {%0,%1},%2;" : "=f"(lo), "=f"(hi) : "l"(v));
}

// ---------------- CSR construction ----------------
__global__ void k_init_deg(int* deg) {
    int i = blockIdx.x * blockDim.x + threadIdx.x;
    if (i < NNODE) deg[i] = 1;  // self loop
}

__global__ void k_count(const int* __restrict__ dst, int* deg) {
    int i = blockIdx.x * blockDim.x + threadIdx.x;
    if (i < NEDGE) atomicAdd(&deg[dst[i]], 1);
}

// multi-block scan: phase 1 (per-block exclusive scan + block sums)
__global__ void k_scan1(const int* __restrict__ deg, int* __restrict__ start,
                        int* __restrict__ bsum, int n) {
    __shared__ int buf[1024];
    int tid = threadIdx.x;
    int i = blockIdx.x * 1024 + tid;
    int v = (i < n) ? deg[i] : 0;
    buf[tid] = v;
    __syncthreads();
    for (int off = 1; off < 1024; off <<= 1) {
        int x = (tid >= off) ? buf[tid - off] : 0;
        __syncthreads();
        buf[tid] += x;
        __syncthreads();
    }
    if (i < n) start[i] = buf[tid] - v;
    if (tid == 1023) bsum[blockIdx.x] = buf[1023];
}

__global__ void k_scan2(int* bsum, int nb) {
    __shared__ int b[64];
    int t = threadIdx.x;
    int v = (t < nb) ? bsum[t] : 0;
    b[t] = v;
    __syncthreads();
    for (int off = 1; off < 64; off <<= 1) {
        int x = (t >= off) ? b[t - off] : 0;
        __syncthreads();
        b[t] += x;
        __syncthreads();
    }
    if (t < nb) bsum[t] = b[t] - v;  // exclusive
}

__global__ void k_scan3(int* __restrict__ start, const int* __restrict__ bsum, int n) {
    int i = blockIdx.x * 1024 + threadIdx.x;
    if (i < n) start[i] += bsum[blockIdx.x];
}

__global__ void k_init_loops(const int* __restrict__ start, int* cursor, int* csr) {
    int i = blockIdx.x * blockDim.x + threadIdx.x;
    if (i < NNODE) {
        int s = start[i];
        csr[s] = i;          // self loop first
        cursor[i] = s + 1;
    }
}

__global__ void k_scatter(const int* __restrict__ src, const int* __restrict__ dst,
                          int* cursor, int* csr) {
    int i = blockIdx.x * blockDim.x + threadIdx.x;
    if (i < NEDGE) {
        int d = dst[i];
        int p = atomicAdd(&cursor[d], 1);
        csr[p] = src[i];
    }
}

// ---------------- BN-fold into weights (natural [k][j] layout out) ----------------
__global__ void k_fold(const float* __restrict__ W, const float* __restrict__ bn_g,
                       const float* __restrict__ bn_b, const float* __restrict__ base,
                       float* __restrict__ Wf, float* __restrict__ biasv) {
    int j = threadIdx.x;
    float bb = base ? base[j] : 0.f;
    const float inv = rsqrtf(1.f + BN_EPS);
    for (int k = 0; k < HID; k++) {
        float w = W[k * HID + j];
        Wf[k * HID + j] = bn_g[k] * inv * w;
        bb += bn_b[k] * w;
    }
    biasv[j] = bb;
}

__global__ void k_fold_cls(const float* __restrict__ W, const float* __restrict__ bn_g,
                           const float* __restrict__ bn_b, const float* __restrict__ base,
                           float* __restrict__ Wt, float* __restrict__ biasv) {
    int j = threadIdx.x;
    if (j >= NCLS) return;
    float bb = base[j];
    const float inv = rsqrtf(1.f + BN_EPS);
    for (int k = 0; k < HID; k++) {
        float w = W[k * NCLS + j];
        Wt[j * HID + k] = bn_g[k] * inv * w;
        bb += bn_b[k] * w;
    }
    biasv[j] = bb;
}

// ---------------- GEMM: C[M,128] = A[M,128] @ Wf[k][j] + bias, f32x2 packed ----------
#define TM 32
__global__ void k_gemm128(const float* __restrict__ A, const float* __restrict__ W,
                          const float* __restrict__ biasv, float* __restrict__ C,
                          int M, int doRelu) {
    __shared__ __align__(8) float sAT[128][TM + 2];  // [k][row], stride 34 (even)
    int tid = threadIdx.x;
    int jg = tid & 31;        // j-group: columns jg*4 .. jg*4+3
    int rg = tid >> 5;        // row-group: rows rg*8 .. rg*8+7 (== warp id)
    int row0 = blockIdx.x * TM;

    // stage A transposed
    const float4* A4 = (const float4*)A;
    for (int idx = tid; idx < TM * 32; idx += 128) {
        int r = idx >> 5;      // row 0..31
        int q = idx & 31;      // k-quad 0..31
        float4 a = make_float4(0.f, 0.f, 0.f, 0.f);
        if (row0 + r < M) a = __ldg(&A4[(row0 + r) * 32 + q]);
        sAT[4 * q + 0][r] = a.x;
        sAT[4 * q + 1][r] = a.y;
        sAT[4 * q + 2][r] = a.z;
        sAT[4 * q + 3][r] = a.w;
    }
    __syncthreads();

    float4 b4 = __ldg(&((const float4*)biasv)[jg]);
    unsigned long long acc[4][4];  // [row-pair p][col c]
#pragma unroll
    for (int p = 0; p < 4; p++) {
        acc[p][0] = pk2(b4.x);
        acc[p][1] = pk2(b4.y);
        acc[p][2] = pk2(b4.z);
        acc[p][3] = pk2(b4.w);
    }

    const float4* W4 = (const float4*)W;
#pragma unroll 4
    for (int k = 0; k < 128; k++) {
        float4 w = __ldg(&W4[k * 32 + jg]);
        unsigned long long w0 = pk2(w.x), w1 = pk2(w.y), w2 = pk2(w.z), w3 = pk2(w.w);
        const unsigned long long* ap = (const unsigned long long*)&sAT[k][rg * 8];
        unsigned long long a0 = ap[0], a1 = ap[1], a2 = ap[2], a3 = ap[3];
        fma2(acc[0][0], a0, w0); fma2(acc[0][1], a0, w1); fma2(acc[0][2], a0, w2); fma2(acc[0][3], a0, w3);
        fma2(acc[1][0], a1, w0); fma2(acc[1][1], a1, w1); fma2(acc[1][2], a1, w2); fma2(acc[1][3], a1, w3);
        fma2(acc[2][0], a2, w0); fma2(acc[2][1], a2, w1); fma2(acc[2][2], a2, w2); fma2(acc[2][3], a2, w3);
        fma2(acc[3][0], a3, w0); fma2(acc[3][1], a3, w1); fma2(acc[3][2], a3, w2); fma2(acc[3][3], a3, w3);
    }

    float4* C4 = (float4*)C;
#pragma unroll
    for (int p = 0; p < 4; p++) {
        float4 r0v, r1v;
        unpk2(acc[p][0], r0v.x, r1v.x);
        unpk2(acc[p][1], r0v.y, r1v.y);
        unpk2(acc[p][2], r0v.z, r1v.z);
        unpk2(acc[p][3], r0v.w, r1v.w);
        if (doRelu) {
            r0v.x = fmaxf(r0v.x, 0.f); r0v.y = fmaxf(r0v.y, 0.f);
            r0v.z = fmaxf(r0v.z, 0.f); r0v.w = fmaxf(r0v.w, 0.f);
            r1v.x = fmaxf(r1v.x, 0.f); r1v.y = fmaxf(r1v.y, 0.f);
            r1v.z = fmaxf(r1v.z, 0.f); r1v.w = fmaxf(r1v.w, 0.f);
        }
        int ra = row0 + rg * 8 + 2 * p;
        if (ra < M)     C4[ra * 32 + jg] = r0v;
        if (ra + 1 < M) C4[(ra + 1) * 32 + jg] = r1v;
    }
}

// ---------------- per-node attention dot precompute ----------------
__device__ __forceinline__ float grp8_sum(float v) {
    v += __shfl_xor_sync(0xffffffffu, v, 1);
    v += __shfl_xor_sync(0xffffffffu, v, 2);
    v += __shfl_xor_sync(0xffffffffu, v, 4);
    return v;
}

__global__ void k_dots(const float* __restrict__ hh, const float* __restrict__ att_l,
                       const float* __restrict__ att_r, float* __restrict__ li,
                       float* __restrict__ ri) {
    int warp = (blockIdx.x * blockDim.x + threadIdx.x) >> 5;
    int lane = threadIdx.x & 31;
    if (warp >= NNODE) return;
    float4 hi = __ldg(&((const float4*)hh)[warp * 32 + lane]);
    float4 al = __ldg(&((const float4*)att_l)[lane]);
    float4 ar = __ldg(&((const float4*)att_r)[lane]);
    float l = hi.x * al.x + hi.y * al.y + hi.z * al.z + hi.w * al.w;
    float r = hi.x * ar.x + hi.y * ar.y + hi.z * ar.z + hi.w * ar.w;
    l = grp8_sum(l);
    r = grp8_sum(r);
    if ((lane & 7) == 0) {
        li[warp * 4 + (lane >> 3)] = l;
        ri[warp * 4 + (lane >> 3)] = r;
    }
}

// ---------------- attention: warp per dst node, online softmax ----------------
__device__ __forceinline__ void amerge(float alpha, const float4& hj,
                                       float& m, float& s, float4& acc) {
    alpha = alpha > 0.f ? alpha : NEG_SLOPE * alpha;  // leaky relu
    float nm = fmaxf(m, alpha);
    float c = __expf(m - nm);
    float w = __expf(alpha - nm);
    s = s * c + w;
    acc.x = acc.x * c + w * hj.x;
    acc.y = acc.y * c + w * hj.y;
    acc.z = acc.z * c + w * hj.z;
    acc.w = acc.w * c + w * hj.w;
    m = nm;
}

__global__ void k_attn(const float* __restrict__ hh, const int* __restrict__ start,
                       const int* __restrict__ deg, const int* __restrict__ csr,
                       const float* __restrict__ li, const float* __restrict__ ri,
                       const float* __restrict__ b_gat, float* __restrict__ out) {
    int warp = (blockIdx.x * blockDim.x + threadIdx.x) >> 5;
    int lane = threadIdx.x & 31;
    if (warp >= NNODE) return;
    int hq = lane >> 3;  // head index
    const float4* hh4 = (const float4*)hh;
    float4 hi = __ldg(&hh4[warp * 32 + lane]);
    float rin = __ldg(&ri[warp * 4 + hq]);

    float m = -INFINITY, s = 0.f;
    float4 acc = make_float4(0.f, 0.f, 0.f, 0.f);
    int e = start[warp];
    int eend = e + deg[warp];

    for (; e + 4 <= eend; e += 4) {
        int s0 = __ldg(&csr[e + 0]);
        int s1 = __ldg(&csr[e + 1]);
        int s2 = __ldg(&csr[e + 2]);
        int s3 = __ldg(&csr[e + 3]);
        float4 h0 = __ldg(&hh4[s0 * 32 + lane]);
        float4 h1 = __ldg(&hh4[s1 * 32 + lane]);
        float4 h2 = __ldg(&hh4[s2 * 32 + lane]);
        float4 h3 = __ldg(&hh4[s3 * 32 + lane]);
        float l0 = __ldg(&li[s0 * 4 + hq]);
        float l1 = __ldg(&li[s1 * 4 + hq]);
        float l2 = __ldg(&li[s2 * 4 + hq]);
        float l3 = __ldg(&li[s3 * 4 + hq]);
        float g0 = grp8_sum(hi.x * h0.x + hi.y * h0.y + hi.z * h0.z + hi.w * h0.w);
        float g1 = grp8_sum(hi.x * h1.x + hi.y * h1.y + hi.z * h1.z + hi.w * h1.w);
        float g2 = grp8_sum(hi.x * h2.x + hi.y * h2.y + hi.z * h2.z + hi.w * h2.w);
        float g3 = grp8_sum(hi.x * h3.x + hi.y * h3.y + hi.z * h3.z + hi.w * h3.w);
        float a0 = __fdividef(l0 + rin, 1.f + __expf(-g0));
        float a1 = __fdividef(l1 + rin, 1.f + __expf(-g1));
        float a2 = __fdividef(l2 + rin, 1.f + __expf(-g2));
        float a3 = __fdividef(l3 + rin, 1.f + __expf(-g3));
        amerge(a0, h0, m, s, acc);
        amerge(a1, h1, m, s, acc);
        amerge(a2, h2, m, s, acc);
        amerge(a3, h3, m, s, acc);
    }
    for (; e < eend; e++) {
        int sn = __ldg(&csr[e]);
        float4 hj = __ldg(&hh4[sn * 32 + lane]);
        float lg = grp8_sum(hi.x * hj.x + hi.y * hj.y + hi.z * hj.z + hi.w * hj.w);
        float lj = __ldg(&li[sn * 4 + hq]);
        float a = __fdividef(lj + rin, 1.f + __expf(-lg));
        amerge(a, hj, m, s, acc);
    }

    float invs = __fdividef(1.f, s + 1e-16f);
    float4 bg = __ldg(&((const float4*)b_gat)[lane]);
    float4 o;
    o.x = fmaxf(acc.x * invs + bg.x, 0.f);
    o.y = fmaxf(acc.y * invs + bg.y, 0.f);
    o.z = fmaxf(acc.z * invs + bg.z, 0.f);
    o.w = fmaxf(acc.w * invs + bg.w, 0.f);
    ((float4*)out)[warp * 32 + lane] = o;
}

// ---------------- pooling (batch is sorted) ----------------
__global__ void k_zero(float* p, int n) {
    int i = blockIdx.x * blockDim.x + threadIdx.x;
    if (i < n) p[i] = 0.f;
}

#define PCHUNK 128
__global__ void k_pool(const float* __restrict__ h, const int* __restrict__ batch,
                       float* __restrict__ g) {
    __shared__ int sb[PCHUNK];
    int c = threadIdx.x;  // 128 channels
    int n0 = blockIdx.x * PCHUNK;
    {
        int idx = n0 + c;
        sb[c] = (idx < NNODE) ? batch[idx] : -1;
    }
    __syncthreads();
    if (sb[0] < 0) return;
    float acc = 0.f;
    int cur = sb[0];
    for (int i = 0; i < PCHUNK; i++) {
        int b = sb[i];
        if (b < 0) break;
        if (b != cur) {
            atomicAdd(&g[cur * HID + c], acc);
            acc = 0.f;
            cur = b;
        }
        acc += h[(n0 + i) * HID + c];
    }
    atomicAdd(&g[cur * HID + c], acc);
}

// ---------------- final logits + log_softmax ----------------
__global__ void k_final(const float* __restrict__ t, const float* __restrict__ Wct,
                        const float* __restrict__ bc, float* __restrict__ out) {
    __shared__ float sr[HID];
    int row = blockIdx.x;
    int lane = threadIdx.x;  // 32
    for (int i = lane; i < HID; i += 32) sr[i] = t[row * HID + i];
    __syncthreads();
    float lg = -INFINITY;
    if (lane < NCLS) {
        float a = bc[lane];
        const float* wr = Wct + lane * HID;
        for (int k = 0; k < HID; k++) a += sr[k] * wr[k];
        lg = a;
    }
    float mx = lg;
    for (int o = 16; o > 0; o >>= 1) mx = fmaxf(mx, __shfl_xor_sync(0xffffffffu, mx, o));
    float ex = (lane < NCLS) ? __expf(lg - mx) : 0.f;
    float sm = ex;
    for (int o = 16; o > 0; o >>= 1) sm += __shfl_xor_sync(0xffffffffu, sm, o);
    if (lane < NCLS) out[row * NCLS + lane] = lg - mx - logf(sm);
}

__global__ void k_zero_tail(float* out, int from, int total) {
    int i = from + blockIdx.x * blockDim.x + threadIdx.x;
    if (i < total) out[i] = 0.f;
}

// ---------------- launch ----------------
static inline void* sym(const void* s) {
    void* p = nullptr;
    cudaGetSymbolAddress(&p, s);
    return p;
}

extern "C" void kernel_launch(void* const* d_in, const int* in_sizes, int n_in,
                              void* d_out, int out_size) {
    const float* x        = (const float*)d_in[0];
    const int*   ei       = (const int*)d_in[1];
    const int*   batch    = (const int*)d_in[2];
    const float* bn_f_g   = (const float*)d_in[3];
    const float* bn_f_b   = (const float*)d_in[4];
    const float* w_feat   = (const float*)d_in[5];
    const float* b_feat   = (const float*)d_in[6];
    const float* bn_c_g   = (const float*)d_in[7];
    const float* bn_c_b   = (const float*)d_in[8];
    const float* w_gat    = (const float*)d_in[9];
    const float* att_l    = (const float*)d_in[10];
    const float* att_r    = (const float*)d_in[11];
    const float* b_gat    = (const float*)d_in[12];
    const float* bn_fc_g  = (const float*)d_in[13];
    const float* bn_fc_b  = (const float*)d_in[14];
    const float* w_fc     = (const float*)d_in[15];
    const float* b_fc     = (const float*)d_in[16];
    const float* bn_h_g   = (const float*)d_in[17];
    const float* bn_h_b   = (const float*)d_in[18];
    const float* w_cls    = (const float*)d_in[19];
    const float* b_cls    = (const float*)d_in[20];
    float* out = (float*)d_out;

    const int* srcp = ei;
    const int* dstp = ei + NEDGE;

    int*   deg    = (int*)sym(g_deg);
    int*   start  = (int*)sym(g_start);
    int*   cursor = (int*)sym(g_cursor);
    int*   bsum   = (int*)sym(g_bsum);
    int*   csr    = (int*)sym(g_csr);
    float* bufA   = (float*)sym(g_bufA);
    float* bufB   = (float*)sym(g_bufB);
    float* hh     = (float*)sym(g_hh);
    float* li     = (float*)sym(g_li);
    float* ri     = (float*)sym(g_ri);
    float* Wf     = (float*)sym(g_Wf);
    float* biasv  = (float*)sym(g_biasv);
    float* pool   = (float*)sym(g_pool);
    float* tmp    = (float*)sym(g_tmp);
    float* Wct    = (float*)sym(g_Wct);
    float* biasc  = (float*)sym(g_biasc);

    // CSR build
    k_init_deg<<<(NNODE + 255) / 256, 256>>>(deg);
    k_count<<<(NEDGE + 255) / 256, 256>>>(dstp, deg);
    k_scan1<<<NB_SCAN, 1024>>>(deg, start, bsum, NNODE);
    k_scan2<<<1, 64>>>(bsum, NB_SCAN);
    k_scan3<<<NB_SCAN, 1024>>>(start, bsum, NNODE);
    k_init_loops<<<(NNODE + 255) / 256, 256>>>(start, cursor, csr);
    k_scatter<<<(NEDGE + 255) / 256, 256>>>(srcp, dstp, cursor, csr);

    // feature layer
    k_fold<<<1, HID>>>(w_feat, bn_f_g, bn_f_b, b_feat, Wf, biasv);
    k_gemm128<<<(NNODE + TM - 1) / TM, 128>>>(x, Wf, biasv, bufA, NNODE, 1);

    float* cur = bufA;
    float* nxt = bufB;
    for (int i = 0; i < 3; i++) {
        k_fold<<<1, HID>>>(w_gat + i * HID * HID, bn_c_g + i * HID, bn_c_b + i * HID,
                           nullptr, Wf, biasv);
        k_gemm128<<<(NNODE + TM - 1) / TM, 128>>>(cur, Wf, biasv, hh, NNODE, 0);
        k_dots<<<(NNODE * 32 + 255) / 256, 256>>>(hh, att_l + i * HID, att_r + i * HID,
                                                  li, ri);
        k_attn<<<(NNODE * 32 + 255) / 256, 256>>>(hh, start, deg, csr, li, ri,
                                                  b_gat + i * HID, nxt);
        float* t2 = cur; cur = nxt; nxt = t2;
    }

    // pooling
    k_zero<<<(NG * HID + 255) / 256, 256>>>(pool, NG * HID);
    k_pool<<<(NNODE + PCHUNK - 1) / PCHUNK, HID>>>(cur, batch, pool);

    // fc
    k_fold<<<1, HID>>>(w_fc, bn_fc_g, bn_fc_b, b_fc, Wf, biasv);
    k_gemm128<<<(NG + TM - 1) / TM, 128>>>(pool, Wf, biasv, tmp, NG, 1);

    // cls + log_softmax
    k_fold_cls<<<1, 32>>>(w_cls, bn_h_g, bn_h_b, b_cls, Wct, biasc);
    k_final<<<NG, 32>>>(tmp, Wct, biasc, out);

    if (out_size > NG * NCLS) {
        int rem = out_size - NG * NCLS;
        k_zero_tail<<<(rem + 255) / 256, 256>>>(out, NG * NCLS, out_size);
    }
}

// round 3
// speedup vs baseline: 2.2295x; 1.2737x over previous
#include <cuda_runtime.h>
#include <cuda_fp16.h>
#include <math.h>

#define NNODE 50000
#define NEDGE 800000
#define E2 (NEDGE + NNODE)
#define HID 128
#define NG 512
#define NCLS 10
#define BN_EPS 1e-5f
#define NEG_SLOPE 0.2f
#define NB_SCAN ((NNODE + 1023) / 1024)

// ---------------- device scratch ----------------
__device__ int     g_deg[NNODE];          // zero-init at load; self-restored each run
__device__ int     g_start[NNODE + 1];
__device__ int     g_cursor[NNODE];
__device__ int     g_bsum[64];
__device__ int     g_csr[E2];
__device__ float   g_bufA[NNODE * HID];
__device__ float   g_bufB[NNODE * HID];
__device__ __half2 g_hh2[NNODE * 64];
__device__ float   g_li[NNODE * 4];
__device__ float   g_ri[NNODE * 4];
__device__ float   g_Wf[5 * HID * HID];
__device__ float   g_biasv[5 * HID];
__device__ float   g_pool[NG * HID];
__device__ float   g_tmp[NG * HID];
__device__ float   g_Wct[NCLS * HID];
__device__ float   g_biasc[NCLS];

// ---------------- packed f32x2 helpers ----------------
__device__ __forceinline__ unsigned long long pk2(float x) {
    unsigned long long r;
    asm("mov.b64 %0,{%1,%1};" : "=l"(r) : "f"(x));
    return r;
}
__device__ __forceinline__ void fma2(unsigned long long& d, unsigned long long a,
                                     unsigned long long b) {
    asm("fma.rn.f32x2 %0,%1,%2,%0;" : "+l"(d) : "l"(a), "l"(b));
}
__device__ __forceinline__ void unpk2(unsigned long long v, float& lo, float& hi) {
    asm("mov.b64 {%0,%1},%2;" : "=f"(lo), "=f"(hi) : "l"(v));
}

// ---------------- CSR construction ----------------
__global__ void k_count(const int* __restrict__ dst, int* deg) {
    int i = blockIdx.x * blockDim.x + threadIdx.x;
    if (i < NEDGE) atomicAdd(&deg[dst[i]], 1);
}

// per-block inclusive scan of (deg+1); restores deg to 0 for the next replay
__global__ void k_scan1(int* __restrict__ deg, int* __restrict__ start,
                        int* __restrict__ bsum, int n) {
    __shared__ int buf[1024];
    int tid = threadIdx.x;
    int i = blockIdx.x * 1024 + tid;
    int v = 0;
    if (i < n) {
        v = deg[i] + 1;   // +1 self loop
        deg[i] = 0;       // restore for next replay
    }
    buf[tid] = v;
    __syncthreads();
    for (int off = 1; off < 1024; off <<= 1) {
        int x = (tid >= off) ? buf[tid - off] : 0;
        __syncthreads();
        buf[tid] += x;
        __syncthreads();
    }
    if (i < n) start[i] = buf[tid] - v;  // exclusive within block
    if (tid == 1023) bsum[blockIdx.x] = buf[1023];
}

__global__ void k_scan2(int* bsum, int nb) {
    __shared__ int b[64];
    int t = threadIdx.x;
    int v = (t < nb) ? bsum[t] : 0;
    b[t] = v;
    __syncthreads();
    for (int off = 1; off < 64; off <<= 1) {
        int x = (t >= off) ? b[t - off] : 0;
        __syncthreads();
        b[t] += x;
        __syncthreads();
    }
    if (t < nb) bsum[t] = b[t] - v;  // exclusive
}

// finish scan + write self-loop + cursor (fused old k_scan3 + k_init_loops)
__global__ void k_scan3(int* __restrict__ start, const int* __restrict__ bsum,
                        int* __restrict__ cursor, int* __restrict__ csr, int n) {
    int i = blockIdx.x * 1024 + threadIdx.x;
    if (i < n) {
        int s = start[i] + bsum[blockIdx.x];
        start[i] = s;
        csr[s] = i;        // self loop first
        cursor[i] = s + 1;
    }
    if (i == 0) start[n] = E2;
}

__global__ void k_scatter(const int* __restrict__ src, const int* __restrict__ dst,
                          int* cursor, int* csr) {
    int i = blockIdx.x * blockDim.x + threadIdx.x;
    if (i < NEDGE) {
        int d = dst[i];
        int p = atomicAdd(&cursor[d], 1);
        csr[p] = src[i];
    }
}

// ---------------- one-shot fold of all layers + zero pool + zero out tail ----------------
// grid layout: [0,645) = 5 layers x (128 weight rows + 1 bias block)
//              [645,655) = 10 cls columns
//              [655,1167) = 512 blocks zeroing pool
//              [1167]     = out tail zero
__global__ void k_fold_all(const float* __restrict__ w_feat, const float* __restrict__ bn_f_g,
                           const float* __restrict__ bn_f_b, const float* __restrict__ b_feat,
                           const float* __restrict__ w_gat, const float* __restrict__ bn_c_g,
                           const float* __restrict__ bn_c_b,
                           const float* __restrict__ w_fc, const float* __restrict__ bn_fc_g,
                           const float* __restrict__ bn_fc_b, const float* __restrict__ b_fc,
                           const float* __restrict__ w_cls, const float* __restrict__ bn_h_g,
                           const float* __restrict__ bn_h_b, const float* __restrict__ b_cls,
                           float* __restrict__ Wf, float* __restrict__ biasv,
                           float* __restrict__ Wct, float* __restrict__ biasc,
                           float* __restrict__ pool, float* __restrict__ out, int out_size) {
    int b = blockIdx.x;
    int j = threadIdx.x;
    const float inv = rsqrtf(1.f + BN_EPS);
    if (b < 645) {
        int L = b / 129, r = b % 129;
        const float *W, *gg, *bb, *base;
        if (L == 0)      { W = w_feat; gg = bn_f_g; bb = bn_f_b; base = b_feat; }
        else if (L <= 3) { W = w_gat + (L - 1) * HID * HID; gg = bn_c_g + (L - 1) * HID;
                           bb = bn_c_b + (L - 1) * HID; base = nullptr; }
        else             { W = w_fc; gg = bn_fc_g; bb = bn_fc_b; base = b_fc; }
        if (r < 128) {
            Wf[L * HID * HID + r * HID + j] = gg[r] * inv * W[r * HID + j];
        } else {
            float acc = base ? base[j] : 0.f;
            for (int k = 0; k < HID; k++) acc += bb[k] * W[k * HID + j];
            biasv[L * HID + j] = acc;
        }
    } else if (b < 655) {
        int cls = b - 645;
        int k = j;
        float w = w_cls[k * NCLS + cls];
        Wct[cls * HID + k] = bn_h_g[k] * inv * w;
        __shared__ float sred[128];
        sred[k] = bn_h_b[k] * w;
        __syncthreads();
        for (int off = 64; off > 0; off >>= 1) {
            if (k < off) sred[k] += sred[k + off];
            __syncthreads();
        }
        if (k == 0) biasc[cls] = sred[0] + b_cls[cls];
    } else if (b < 1167) {
        int i = (b - 655) * 128 + j;
        if (i < NG * HID) pool[i] = 0.f;
    } else {
        for (int t = NG * NCLS + j; t < out_size; t += 128) out[t] = 0.f;
    }
}

// ---------------- shfl helpers ----------------
__device__ __forceinline__ float grp8_sum(float v) {
    v += __shfl_xor_sync(0xffffffffu, v, 1);
    v += __shfl_xor_sync(0xffffffffu, v, 2);
    v += __shfl_xor_sync(0xffffffffu, v, 4);
    return v;
}

// ---------------- GEMM: C[M,128] = A[M,128] @ Wf[k][j] + bias ----------------
// MODE 0: fp32 out + relu.  MODE 1: fp16 hh2 out + fused li/ri dots (no relu).
#define TM 32
template <int MODE>
__global__ void k_gemm128(const float* __restrict__ A, const float* __restrict__ W,
                          const float* __restrict__ biasv, float* __restrict__ Cout,
                          __half2* __restrict__ hh2, float* __restrict__ li,
                          float* __restrict__ ri, const float* __restrict__ att_l,
                          const float* __restrict__ att_r, int M) {
    __shared__ __align__(8) float sAT[128][TM + 2];
    int tid = threadIdx.x;
    int jg = tid & 31;
    int rg = tid >> 5;
    int row0 = blockIdx.x * TM;

    const float4* A4 = (const float4*)A;
    for (int idx = tid; idx < TM * 32; idx += 128) {
        int r = idx >> 5;
        int q = idx & 31;
        float4 a = make_float4(0.f, 0.f, 0.f, 0.f);
        if (row0 + r < M) a = __ldg(&A4[(row0 + r) * 32 + q]);
        sAT[4 * q + 0][r] = a.x;
        sAT[4 * q + 1][r] = a.y;
        sAT[4 * q + 2][r] = a.z;
        sAT[4 * q + 3][r] = a.w;
    }
    __syncthreads();

    float4 b4 = __ldg(&((const float4*)biasv)[jg]);
    unsigned long long acc[4][4];
#pragma unroll
    for (int p = 0; p < 4; p++) {
        acc[p][0] = pk2(b4.x);
        acc[p][1] = pk2(b4.y);
        acc[p][2] = pk2(b4.z);
        acc[p][3] = pk2(b4.w);
    }

    const float4* W4 = (const float4*)W;
#pragma unroll 4
    for (int k = 0; k < 128; k++) {
        float4 w = __ldg(&W4[k * 32 + jg]);
        unsigned long long w0 = pk2(w.x), w1 = pk2(w.y), w2 = pk2(w.z), w3 = pk2(w.w);
        const unsigned long long* ap = (const unsigned long long*)&sAT[k][rg * 8];
        unsigned long long a0 = ap[0], a1 = ap[1], a2 = ap[2], a3 = ap[3];
        fma2(acc[0][0], a0, w0); fma2(acc[0][1], a0, w1); fma2(acc[0][2], a0, w2); fma2(acc[0][3], a0, w3);
        fma2(acc[1][0], a1, w0); fma2(acc[1][1], a1, w1); fma2(acc[1][2], a1, w2); fma2(acc[1][3], a1, w3);
        fma2(acc[2][0], a2, w0); fma2(acc[2][1], a2, w1); fma2(acc[2][2], a2, w2); fma2(acc[2][3], a2, w3);
        fma2(acc[3][0], a3, w0); fma2(acc[3][1], a3, w1); fma2(acc[3][2], a3, w2); fma2(acc[3][3], a3, w3);
    }

    if (MODE == 0) {
        float4* C4 = (float4*)Cout;
#pragma unroll
        for (int p = 0; p < 4; p++) {
            float4 r0v, r1v;
            unpk2(acc[p][0], r0v.x, r1v.x);
            unpk2(acc[p][1], r0v.y, r1v.y);
            unpk2(acc[p][2], r0v.z, r1v.z);
            unpk2(acc[p][3], r0v.w, r1v.w);
            r0v.x = fmaxf(r0v.x, 0.f); r0v.y = fmaxf(r0v.y, 0.f);
            r0v.z = fmaxf(r0v.z, 0.f); r0v.w = fmaxf(r0v.w, 0.f);
            r1v.x = fmaxf(r1v.x, 0.f); r1v.y = fmaxf(r1v.y, 0.f);
            r1v.z = fmaxf(r1v.z, 0.f); r1v.w = fmaxf(r1v.w, 0.f);
            int ra = row0 + rg * 8 + 2 * p;
            if (ra < M)     C4[ra * 32 + jg] = r0v;
            if (ra + 1 < M) C4[(ra + 1) * 32 + jg] = r1v;
        }
    } else {
        float4 al4 = __ldg(&((const float4*)att_l)[jg]);
        float4 ar4 = __ldg(&((const float4*)att_r)[jg]);
        int head = jg >> 3;
        uint2* hh2u = (uint2*)hh2;
#pragma unroll
        for (int p = 0; p < 4; p++) {
            float4 r0v, r1v;
            unpk2(acc[p][0], r0v.x, r1v.x);
            unpk2(acc[p][1], r0v.y, r1v.y);
            unpk2(acc[p][2], r0v.z, r1v.z);
            unpk2(acc[p][3], r0v.w, r1v.w);
            int ra = row0 + rg * 8 + 2 * p;
            // fp16 store
            if (ra < M) {
                __half2 ha = __floats2half2_rn(r0v.x, r0v.y);
                __half2 hb = __floats2half2_rn(r0v.z, r0v.w);
                uint2 u;
                u.x = *(unsigned*)&ha;
                u.y = *(unsigned*)&hb;
                hh2u[ra * 32 + jg] = u;
            }
            if (ra + 1 < M) {
                __half2 ha = __floats2half2_rn(r1v.x, r1v.y);
                __half2 hb = __floats2half2_rn(r1v.z, r1v.w);
                uint2 u;
                u.x = *(unsigned*)&ha;
                u.y = *(unsigned*)&hb;
                hh2u[(ra + 1) * 32 + jg] = u;
            }
            // fused att dots (exact fp32)
            float l0 = r0v.x * al4.x + r0v.y * al4.y + r0v.z * al4.z + r0v.w * al4.w;
            float l1 = r1v.x * al4.x + r1v.y * al4.y + r1v.z * al4.z + r1v.w * al4.w;
            float q0 = r0v.x * ar4.x + r0v.y * ar4.y + r0v.z * ar4.z + r0v.w * ar4.w;
            float q1 = r1v.x * ar4.x + r1v.y * ar4.y + r1v.z * ar4.z + r1v.w * ar4.w;
            l0 = grp8_sum(l0); l1 = grp8_sum(l1);
            q0 = grp8_sum(q0); q1 = grp8_sum(q1);
            if ((jg & 7) == 0) {
                if (ra < M)     { li[ra * 4 + head] = l0;       ri[ra * 4 + head] = q0; }
                if (ra + 1 < M) { li[(ra + 1) * 4 + head] = l1; ri[(ra + 1) * 4 + head] = q1; }
            }
        }
    }
}

// ---------------- attention: warp per dst node, online softmax, fp16 gathers ----------
__device__ __forceinline__ float4 ld_h4(const uint2* __restrict__ hh2u, int node, int lane) {
    uint2 u = __ldg(&hh2u[node * 32 + lane]);
    __half2 ha = *(__half2*)&u.x;
    __half2 hb = *(__half2*)&u.y;
    float2 f01 = __half22float2(ha);
    float2 f23 = __half22float2(hb);
    return make_float4(f01.x, f01.y, f23.x, f23.y);
}

__device__ __forceinline__ void amerge(float alpha, const float4& hj,
                                       float& m, float& s, float4& acc) {
    alpha = alpha > 0.f ? alpha : NEG_SLOPE * alpha;
    float nm = fmaxf(m, alpha);
    float c = __expf(m - nm);
    float w = __expf(alpha - nm);
    s = s * c + w;
    acc.x = acc.x * c + w * hj.x;
    acc.y = acc.y * c + w * hj.y;
    acc.z = acc.z * c + w * hj.z;
    acc.w = acc.w * c + w * hj.w;
    m = nm;
}

__global__ void k_attn(const __half2* __restrict__ hh2, const int* __restrict__ start,
                       const int* __restrict__ csr, const float* __restrict__ li,
                       const float* __restrict__ ri, const float* __restrict__ b_gat,
                       float* __restrict__ out) {
    int warp = (blockIdx.x * blockDim.x + threadIdx.x) >> 5;
    int lane = threadIdx.x & 31;
    if (warp >= NNODE) return;
    int hq = lane >> 3;
    const uint2* hh2u = (const uint2*)hh2;
    float4 hi = ld_h4(hh2u, warp, lane);
    float rin = __ldg(&ri[warp * 4 + hq]);

    float m = -INFINITY, s = 0.f;
    float4 acc = make_float4(0.f, 0.f, 0.f, 0.f);
    int e = start[warp];
    int eend = start[warp + 1];

    for (; e + 4 <= eend; e += 4) {
        int s0 = __ldg(&csr[e + 0]);
        int s1 = __ldg(&csr[e + 1]);
        int s2 = __ldg(&csr[e + 2]);
        int s3 = __ldg(&csr[e + 3]);
        float4 h0 = ld_h4(hh2u, s0, lane);
        float4 h1 = ld_h4(hh2u, s1, lane);
        float4 h2 = ld_h4(hh2u, s2, lane);
        float4 h3 = ld_h4(hh2u, s3, lane);
        float l0 = __ldg(&li[s0 * 4 + hq]);
        float l1 = __ldg(&li[s1 * 4 + hq]);
        float l2 = __ldg(&li[s2 * 4 + hq]);
        float l3 = __ldg(&li[s3 * 4 + hq]);
        float g0 = grp8_sum(hi.x * h0.x + hi.y * h0.y + hi.z * h0.z + hi.w * h0.w);
        float g1 = grp8_sum(hi.x * h1.x + hi.y * h1.y + hi.z * h1.z + hi.w * h1.w);
        float g2 = grp8_sum(hi.x * h2.x + hi.y * h2.y + hi.z * h2.z + hi.w * h2.w);
        float g3 = grp8_sum(hi.x * h3.x + hi.y * h3.y + hi.z * h3.z + hi.w * h3.w);
        float a0 = __fdividef(l0 + rin, 1.f + __expf(-g0));
        float a1 = __fdividef(l1 + rin, 1.f + __expf(-g1));
        float a2 = __fdividef(l2 + rin, 1.f + __expf(-g2));
        float a3 = __fdividef(l3 + rin, 1.f + __expf(-g3));
        amerge(a0, h0, m, s, acc);
        amerge(a1, h1, m, s, acc);
        amerge(a2, h2, m, s, acc);
        amerge(a3, h3, m, s, acc);
    }
    for (; e < eend; e++) {
        int sn = __ldg(&csr[e]);
        float4 hj = ld_h4(hh2u, sn, lane);
        float lg = grp8_sum(hi.x * hj.x + hi.y * hj.y + hi.z * hj.z + hi.w * hj.w);
        float lj = __ldg(&li[sn * 4 + hq]);
        float a = __fdividef(lj + rin, 1.f + __expf(-lg));
        amerge(a, hj, m, s, acc);
    }

    float invs = __fdividef(1.f, s + 1e-16f);
    float4 bg = __ldg(&((const float4*)b_gat)[lane]);
    float4 o;
    o.x = fmaxf(acc.x * invs + bg.x, 0.f);
    o.y = fmaxf(acc.y * invs + bg.y, 0.f);
    o.z = fmaxf(acc.z * invs + bg.z, 0.f);
    o.w = fmaxf(acc.w * invs + bg.w, 0.f);
    ((float4*)out)[warp * 32 + lane] = o;
}

// ---------------- pooling (batch is sorted) ----------------
#define PCHUNK 128
__global__ void k_pool(const float* __restrict__ h, const int* __restrict__ batch,
                       float* __restrict__ g) {
    __shared__ int sb[PCHUNK];
    int c = threadIdx.x;
    int n0 = blockIdx.x * PCHUNK;
    {
        int idx = n0 + c;
        sb[c] = (idx < NNODE) ? batch[idx] : -1;
    }
    __syncthreads();
    if (sb[0] < 0) return;
    float acc = 0.f;
    int cur = sb[0];
    for (int i = 0; i < PCHUNK; i++) {
        int b = sb[i];
        if (b < 0) break;
        if (b != cur) {
            atomicAdd(&g[cur * HID + c], acc);
            acc = 0.f;
            cur = b;
        }
        acc += h[(n0 + i) * HID + c];
    }
    atomicAdd(&g[cur * HID + c], acc);
}

// ---------------- final logits + log_softmax ----------------
__global__ void k_final(const float* __restrict__ t, const float* __restrict__ Wct,
                        const float* __restrict__ bc, float* __restrict__ out) {
    __shared__ float sr[HID];
    int row = blockIdx.x;
    int lane = threadIdx.x;
    for (int i = lane; i < HID; i += 32) sr[i] = t[row * HID + i];
    __syncthreads();
    float lg = -INFINITY;
    if (lane < NCLS) {
        float a = bc[lane];
        const float* wr = Wct + lane * HID;
        for (int k = 0; k < HID; k++) a += sr[k] * wr[k];
        lg = a;
    }
    float mx = lg;
    for (int o = 16; o > 0; o >>= 1) mx = fmaxf(mx, __shfl_xor_sync(0xffffffffu, mx, o));
    float ex = (lane < NCLS) ? __expf(lg - mx) : 0.f;
    float sm = ex;
    for (int o = 16; o > 0; o >>= 1) sm += __shfl_xor_sync(0xffffffffu, sm, o);
    if (lane < NCLS) out[row * NCLS + lane] = lg - mx - logf(sm);
}

// ---------------- launch ----------------
static inline void* sym(const void* s) {
    void* p = nullptr;
    cudaGetSymbolAddress(&p, s);
    return p;
}

extern "C" void kernel_launch(void* const* d_in, const int* in_sizes, int n_in,
                              void* d_out, int out_size) {
    const float* x        = (const float*)d_in[0];
    const int*   ei       = (const int*)d_in[1];
    const int*   batch    = (const int*)d_in[2];
    const float* bn_f_g   = (const float*)d_in[3];
    const float* bn_f_b   = (const float*)d_in[4];
    const float* w_feat   = (const float*)d_in[5];
    const float* b_feat   = (const float*)d_in[6];
    const float* bn_c_g   = (const float*)d_in[7];
    const float* bn_c_b   = (const float*)d_in[8];
    const float* w_gat    = (const float*)d_in[9];
    const float* att_l    = (const float*)d_in[10];
    const float* att_r    = (const float*)d_in[11];
    const float* b_gat    = (const float*)d_in[12];
    const float* bn_fc_g  = (const float*)d_in[13];
    const float* bn_fc_b  = (const float*)d_in[14];
    const float* w_fc     = (const float*)d_in[15];
    const float* b_fc     = (const float*)d_in[16];
    const float* bn_h_g   = (const float*)d_in[17];
    const float* bn_h_b   = (const float*)d_in[18];
    const float* w_cls    = (const float*)d_in[19];
    const float* b_cls    = (const float*)d_in[20];
    float* out = (float*)d_out;

    const int* srcp = ei;
    const int* dstp = ei + NEDGE;

    int*     deg    = (int*)sym(g_deg);
    int*     start  = (int*)sym(g_start);
    int*     cursor = (int*)sym(g_cursor);
    int*     bsum   = (int*)sym(g_bsum);
    int*     csr    = (int*)sym(g_csr);
    float*   bufA   = (float*)sym(g_bufA);
    float*   bufB   = (float*)sym(g_bufB);
    __half2* hh2    = (__half2*)sym(g_hh2);
    float*   li     = (float*)sym(g_li);
    float*   ri     = (float*)sym(g_ri);
    float*   Wf     = (float*)sym(g_Wf);
    float*   biasv  = (float*)sym(g_biasv);
    float*   pool   = (float*)sym(g_pool);
    float*   tmp    = (float*)sym(g_tmp);
    float*   Wct    = (float*)sym(g_Wct);
    float*   biasc  = (float*)sym(g_biasc);

    // CSR build (deg self-restores to 0 inside k_scan1)
    k_count<<<(NEDGE + 255) / 256, 256>>>(dstp, deg);
    k_fold_all<<<1168, 128>>>(w_feat, bn_f_g, bn_f_b, b_feat,
                              w_gat, bn_c_g, bn_c_b,
                              w_fc, bn_fc_g, bn_fc_b, b_fc,
                              w_cls, bn_h_g, bn_h_b, b_cls,
                              Wf, biasv, Wct, biasc, pool, out, out_size);
    k_scan1<<<NB_SCAN, 1024>>>(deg, start, bsum, NNODE);
    k_scan2<<<1, 64>>>(bsum, NB_SCAN);
    k_scan3<<<NB_SCAN, 1024>>>(start, bsum, cursor, csr, NNODE);
    k_scatter<<<(NEDGE + 255) / 256, 256>>>(srcp, dstp, cursor, csr);

    // feature layer
    k_gemm128<0><<<(NNODE + TM - 1) / TM, 128>>>(x, Wf, biasv, bufA,
                                                 nullptr, nullptr, nullptr,
                                                 nullptr, nullptr, NNODE);

    float* cur = bufA;
    float* nxt = bufB;
    for (int i = 0; i < 3; i++) {
        int L = 1 + i;
        k_gemm128<1><<<(NNODE + TM - 1) / TM, 128>>>(cur, Wf + L * HID * HID,
                                                     biasv + L * HID, nullptr,
                                                     hh2, li, ri,
                                                     att_l + i * HID, att_r + i * HID,
                                                     NNODE);
        k_attn<<<(NNODE * 32 + 255) / 256, 256>>>(hh2, start, csr, li, ri,
                                                  b_gat + i * HID, nxt);
        float* t2 = cur; cur = nxt; nxt = t2;
    }

    // pooling (pool zeroed in k_fold_all)
    k_pool<<<(NNODE + PCHUNK - 1) / PCHUNK, HID>>>(cur, batch, pool);

    // fc
    k_gemm128<0><<<(NG + TM - 1) / TM, 128>>>(pool, Wf + 4 * HID * HID,
                                              biasv + 4 * HID, tmp,
                                              nullptr, nullptr, nullptr,
                                              nullptr, nullptr, NG);

    // cls + log_softmax
    k_final<<<NG, 32>>>(tmp, Wct, biasc, out);
}